// round 6
// baseline (speedup 1.0000x reference)
#include <cuda_runtime.h>
#include <cuda_bf16.h>

#define BB   16
#define NN   16384
#define RR   1024
#define DD   320
#define BINS 32
#define HH   512
#define EPSV 1e-5f

// ---------------- scratch (device globals; no allocation allowed) ----------------
__device__ float g_S[BB * RR * BINS];   // segment bin sums (2 MB)
__device__ int   g_cnt[RR];             // segment counts
__device__ int   g_off[RR];             // exclusive prefix of counts
__device__ float g_W2p[3 * HH];         // folded W2, SoA [c][h]
__device__ float g_b2p[3];

// ---------------- kernel 0: zero accumulators ----------------
__global__ void zero_kernel() {
    int idx = blockIdx.x * blockDim.x + threadIdx.x;
    if (idx < BB * RR * BINS) g_S[idx] = 0.0f;
    if (idx < RR) g_cnt[idx] = 0;
}

// ---------------- kernel 1: segment counts ----------------
__global__ void count_kernel(const int* __restrict__ seg) {
    int i = blockIdx.x * blockDim.x + threadIdx.x;
    if (i < NN) atomicAdd(&g_cnt[seg[i]], 1);
}

// ---------------- kernel 2: per-row 10-wide bin sums + segment atomics ----------------
__global__ __launch_bounds__(256) void binsum_kernel(const float* __restrict__ x,
                                                     const int* __restrict__ seg) {
    __shared__ float4 smf4[16 * 80];   // 16 rows x 320 floats = 20KB
    float* sm = (float*)smf4;
    int row0 = blockIdx.x * 16;
    const float4* x4 = (const float4*)x;
#pragma unroll
    for (int k = 0; k < 5; k++) {
        int e = k * 256 + threadIdx.x;          // 0..1279
        int rr = e / 80, c4 = e % 80;
        smf4[rr * 80 + c4] = x4[(size_t)(row0 + rr) * 80 + c4];
    }
    __syncthreads();
#pragma unroll
    for (int t = 0; t < 2; t++) {
        int task = t * 256 + threadIdx.x;       // 0..511 = 16 rows x 32 bins
        int rr = task >> 5, bin = task & 31;
        int row = row0 + rr;
        int b = row >> 14;                      // row / NN
        int i = row & (NN - 1);
        float s = 0.0f;
#pragma unroll
        for (int j = 0; j < 10; j++) s += sm[rr * 320 + bin * 10 + j];
        atomicAdd(&g_S[((b << 10) + seg[i]) * BINS + bin], s);
    }
}

// ---------------- kernel 3: exclusive prefix sum of counts (1 block) ----------------
__global__ __launch_bounds__(RR) void scan_kernel() {
    __shared__ int sh[RR];
    int t = threadIdx.x;
    int v = g_cnt[t];
    sh[t] = v;
    __syncthreads();
    for (int off = 1; off < RR; off <<= 1) {
        int a = (t >= off) ? sh[t - off] : 0;
        __syncthreads();
        sh[t] += a;
        __syncthreads();
    }
    g_off[t] = sh[t] - v;
}

// ---------------- kernel 4: fold batchnorm into W2 ----------------
__global__ void w2p_kernel(const float* __restrict__ gamma, const float* __restrict__ beta,
                           const float* __restrict__ bn_mean, const float* __restrict__ bn_var,
                           const float* __restrict__ W2, const float* __restrict__ b2) {
    __shared__ float red[HH];
    int h = threadIdx.x;
    float s = rsqrtf(bn_var[h] + EPSV) * gamma[h];
    float t = beta[h] - bn_mean[h] * s;
    for (int c = 0; c < 3; c++) {
        g_W2p[c * HH + h] = W2[h * 3 + c] * s;
        red[h] = t * W2[h * 3 + c];
        __syncthreads();
        for (int off = 256; off; off >>= 1) {
            if (h < off) red[h] += red[h + off];
            __syncthreads();
        }
        if (h == 0) g_b2p[c] = b2[c] + red[0];
        __syncthreads();
    }
}

// ---------------- kernel 5: mega — block per segment ----------------
// Phase U: Us[16][512] = pooled[16][32] @ W1[0:32,:]        (smem)
// Phase B: per chunk of 4 atoms: Vs = cond@W1c+b1 (smem), then
//          out[b,i,:] = relu(Us[b,:]+Vs[il,:]) @ W2p + b2p
// Dyn smem: Us 16*129 f4 (33024) + Vs 4*128 f4 (8192) + W2s 3*128 f4 (6144)
//           + pooled 512 f (2048) = 49408 bytes
#define MEGA_SMEM 49408

__global__ __launch_bounds__(256) void mega_kernel(const float* __restrict__ cond,
                                                   const float* __restrict__ W1,
                                                   const float* __restrict__ b1,
                                                   float* __restrict__ out) {
    extern __shared__ float4 dyn[];
    float4* Us4   = dyn;                    // [16][129]
    float4* Vs4   = Us4 + 16 * 129;         // [4][128]
    float4* W2s4  = Vs4 + 4 * 128;          // [3][128]
    float*  pooled = (float*)(W2s4 + 3 * 128);  // [16][32]

    int r = blockIdx.x;
    int cnt = g_cnt[r];
    if (cnt == 0) return;
    int start = g_off[r];
    int tid = threadIdx.x;

    // pooled + W2p into smem
    float inv = 1.0f / (10.0f * (float)cnt);
    for (int e = tid; e < BB * BINS; e += 256) {
        int b = e >> 5, bin = e & 31;
        pooled[e] = g_S[(size_t)((b << 10) + r) * BINS + bin] * inv;
    }
    for (int e = tid; e < 3 * 128; e += 256)          // FIX: full 384 float4
        W2s4[e] = ((const float4*)g_W2p)[e];
    __syncthreads();

    // ---- phase U: thread owns (hq = tid&127, bhalf = tid>>7), 8 b-accumulators ----
    {
        int hq = tid & 127, bh = tid >> 7;
        const float4* W1v = (const float4*)W1;
        float4 acc[8];
#pragma unroll
        for (int k = 0; k < 8; k++) acc[k] = make_float4(0.f, 0.f, 0.f, 0.f);
#pragma unroll 4
        for (int bin = 0; bin < BINS; bin++) {
            float4 w = W1v[bin * 128 + hq];
#pragma unroll
            for (int k = 0; k < 8; k++) {
                float p = pooled[(bh * 8 + k) * BINS + bin];
                acc[k].x = fmaf(p, w.x, acc[k].x);
                acc[k].y = fmaf(p, w.y, acc[k].y);
                acc[k].z = fmaf(p, w.z, acc[k].z);
                acc[k].w = fmaf(p, w.w, acc[k].w);
            }
        }
#pragma unroll
        for (int k = 0; k < 8; k++) Us4[(bh * 8 + k) * 129 + hq] = acc[k];
    }
    __syncthreads();

    const float4* W1c = (const float4*)(W1 + BINS * HH);
    const float4* b14 = (const float4*)b1;
    float bp0 = g_b2p[0], bp1 = g_b2p[1], bp2 = g_b2p[2];

    // ---- phase B: chunks of 4 atoms ----
    for (int c0 = 0; c0 < cnt; c0 += 4) {
        int nc = min(4, cnt - c0);
        // build Vs for this chunk
        for (int e = tid; e < nc * 128; e += 256) {
            int il = e >> 7, hq = e & 127;
            int i = start + c0 + il;
            float cc0 = __ldg(&cond[i * 3 + 0]);
            float cc1 = __ldg(&cond[i * 3 + 1]);
            float cc2 = __ldg(&cond[i * 3 + 2]);
            float4 w0 = W1c[hq], w1 = W1c[128 + hq], w2 = W1c[256 + hq], bv = b14[hq];
            float4 v;
            v.x = fmaf(cc0, w0.x, fmaf(cc1, w1.x, fmaf(cc2, w2.x, bv.x)));
            v.y = fmaf(cc0, w0.y, fmaf(cc1, w1.y, fmaf(cc2, w2.y, bv.y)));
            v.z = fmaf(cc0, w0.z, fmaf(cc1, w1.z, fmaf(cc2, w2.z, bv.z)));
            v.w = fmaf(cc0, w0.w, fmaf(cc1, w1.w, fmaf(cc2, w2.w, bv.w)));
            Vs4[il * 128 + hq] = v;
        }
        __syncthreads();

        int q = tid & 3, bbi = (tid >> 2) & 15, il = tid >> 6;
        if (il < nc) {
            int i = start + c0 + il;
            const float4* Ub = Us4 + bbi * 129;
            const float4* Vb = Vs4 + il * 128;
            float a0 = 0.f, a1 = 0.f, a2 = 0.f;
            int h0 = q * 32;
#pragma unroll 8
            for (int hq = h0; hq < h0 + 32; hq++) {
                float4 u = Ub[hq], v = Vb[hq];
                float4 w0 = W2s4[hq], w1 = W2s4[128 + hq], w2 = W2s4[256 + hq];
                float z;
                z = fmaxf(u.x + v.x, 0.f); a0 = fmaf(z, w0.x, a0); a1 = fmaf(z, w1.x, a1); a2 = fmaf(z, w2.x, a2);
                z = fmaxf(u.y + v.y, 0.f); a0 = fmaf(z, w0.y, a0); a1 = fmaf(z, w1.y, a1); a2 = fmaf(z, w2.y, a2);
                z = fmaxf(u.z + v.z, 0.f); a0 = fmaf(z, w0.z, a0); a1 = fmaf(z, w1.z, a1); a2 = fmaf(z, w2.z, a2);
                z = fmaxf(u.w + v.w, 0.f); a0 = fmaf(z, w0.w, a0); a1 = fmaf(z, w1.w, a1); a2 = fmaf(z, w2.w, a2);
            }
            // reduce across the 4 h-quarters (4 consecutive lanes)
            a0 += __shfl_xor_sync(0xffffffffu, a0, 1);
            a0 += __shfl_xor_sync(0xffffffffu, a0, 2);
            a1 += __shfl_xor_sync(0xffffffffu, a1, 1);
            a1 += __shfl_xor_sync(0xffffffffu, a1, 2);
            a2 += __shfl_xor_sync(0xffffffffu, a2, 1);
            a2 += __shfl_xor_sync(0xffffffffu, a2, 2);
            if (q == 0) {
                size_t o = ((size_t)bbi * NN + i) * 3;
                out[o + 0] = a0 + bp0;
                out[o + 1] = a1 + bp1;
                out[o + 2] = a2 + bp2;
            }
        }
        __syncthreads();
    }
}

// ---------------- launch ----------------
extern "C" void kernel_launch(void* const* d_in, const int* in_sizes, int n_in,
                              void* d_out, int out_size) {
    const float* x       = (const float*)d_in[0];
    const float* cond    = (const float*)d_in[1];
    const int*   seg     = (const int*)  d_in[2];
    const float* W1      = (const float*)d_in[3];
    const float* b1      = (const float*)d_in[4];
    const float* gamma   = (const float*)d_in[5];
    const float* beta    = (const float*)d_in[6];
    const float* bn_mean = (const float*)d_in[7];
    const float* bn_var  = (const float*)d_in[8];
    const float* W2      = (const float*)d_in[9];
    const float* b2      = (const float*)d_in[10];
    float* out = (float*)d_out;

    cudaFuncSetAttribute(mega_kernel, cudaFuncAttributeMaxDynamicSharedMemorySize, MEGA_SMEM);

    zero_kernel<<<(BB * RR * BINS + 255) / 256, 256>>>();
    count_kernel<<<NN / 256, 256>>>(seg);
    binsum_kernel<<<(BB * NN) / 16, 256>>>(x, seg);
    scan_kernel<<<1, RR>>>();
    w2p_kernel<<<1, HH>>>(gamma, beta, bn_mean, bn_var, W2, b2);
    mega_kernel<<<RR, 256, MEGA_SMEM>>>(cond, W1, b1, out);
}

// round 9
// speedup vs baseline: 1.9174x; 1.9174x over previous
#include <cuda_runtime.h>
#include <cuda_bf16.h>

#define BB   16
#define NN   16384
#define RR   1024
#define DD   320
#define BINS 32
#define HH   512
#define EPSV 1e-5f

// ---------------- scratch (device globals; no allocation allowed) ----------------
__device__ float g_S[BB * RR * BINS];        // segment bin sums (2 MB), [br][bin]
__device__ int   g_cnt[RR];                  // segment counts
__device__ float g_U[(size_t)BB * RR * HH];  // pooled @ W1[0:32]   (33.5 MB)
__device__ float g_V[(size_t)NN * HH];       // cond @ W1[32:35]+b1 (33.5 MB)
__device__ float g_W2p[3 * HH];              // folded W2, SoA [c][h]
__device__ float g_b2p[3];

// ---------------- kernel 0: zero accumulators ----------------
__global__ void zero_kernel() {
    int idx = blockIdx.x * blockDim.x + threadIdx.x;
    if (idx < BB * RR * BINS) g_S[idx] = 0.0f;
    if (idx < RR) g_cnt[idx] = 0;
}

// ---------------- kernel 1: segment counts ----------------
__global__ void count_kernel(const int* __restrict__ seg) {
    int i = blockIdx.x * blockDim.x + threadIdx.x;
    if (i < NN) atomicAdd(&g_cnt[seg[i]], 1);
}

// ---------------- kernel 2: per-row 10-wide bin sums + segment atomics ----------------
__global__ __launch_bounds__(256) void binsum_kernel(const float* __restrict__ x,
                                                     const int* __restrict__ seg) {
    __shared__ float4 smf4[16 * 80];   // 16 rows x 320 floats = 20KB
    float* sm = (float*)smf4;
    int row0 = blockIdx.x * 16;
    const float4* x4 = (const float4*)x;
#pragma unroll
    for (int k = 0; k < 5; k++) {
        int e = k * 256 + threadIdx.x;          // 0..1279
        int rr = e / 80, c4 = e % 80;
        smf4[rr * 80 + c4] = x4[(size_t)(row0 + rr) * 80 + c4];
    }
    __syncthreads();
#pragma unroll
    for (int t = 0; t < 2; t++) {
        int task = t * 256 + threadIdx.x;       // 0..511 = 16 rows x 32 bins
        int rr = task >> 5, bin = task & 31;
        int row = row0 + rr;
        int b = row >> 14;                      // row / NN
        int i = row & (NN - 1);
        float s = 0.0f;
#pragma unroll
        for (int j = 0; j < 10; j++) s += sm[rr * 320 + bin * 10 + j];
        atomicAdd(&g_S[((b << 10) + seg[i]) * BINS + bin], s);
    }
}

// ---------------- kernel 3: fold batchnorm into W2 ----------------
__global__ void w2p_kernel(const float* __restrict__ gamma, const float* __restrict__ beta,
                           const float* __restrict__ bn_mean, const float* __restrict__ bn_var,
                           const float* __restrict__ W2, const float* __restrict__ b2) {
    __shared__ float red[HH];
    int h = threadIdx.x;
    float s = rsqrtf(bn_var[h] + EPSV) * gamma[h];
    float t = beta[h] - bn_mean[h] * s;
    for (int c = 0; c < 3; c++) {
        g_W2p[c * HH + h] = W2[h * 3 + c] * s;
        red[h] = t * W2[h * 3 + c];
        __syncthreads();
        for (int off = 256; off; off >>= 1) {
            if (h < off) red[h] += red[h + off];
            __syncthreads();
        }
        if (h == 0) g_b2p[c] = b2[c] + red[0];
        __syncthreads();
    }
}

// ---------------- kernel 4: tiled U = pooled @ W1[0:32,:] ----------------
// block: 256 threads, 32 br-rows. thread: h4 = tid&127 (covers all 512 h as float4),
// rg = tid>>7 -> 16 rows, acc in 16 float4 registers. W1 via LDG (L1/L2-hot),
// pooled via smem broadcast.
__global__ __launch_bounds__(256) void u_kernel(const float* __restrict__ W1) {
    __shared__ float pooled[32 * BINS];   // [row][bin], 4KB
    int tid = threadIdx.x;
    int br0 = blockIdx.x * 32;

    // load + scale pooled rows (coalesced on bin)
#pragma unroll
    for (int k = 0; k < 4; k++) {
        int e = k * 256 + tid;                  // 0..1023
        int row = e >> 5, bin = e & 31;
        int br = br0 + row;
        int r = br & (RR - 1);
        float c = (float)max(g_cnt[r], 1);
        pooled[e] = g_S[(size_t)br * BINS + bin] * (1.0f / (10.0f * c));
    }
    __syncthreads();

    int h4 = tid & 127, rg = tid >> 7;          // rg in {0,1}
    const float4* W1v = (const float4*)W1;
    float4 acc[16];
#pragma unroll
    for (int k = 0; k < 16; k++) acc[k] = make_float4(0.f, 0.f, 0.f, 0.f);

#pragma unroll 2
    for (int bin = 0; bin < BINS; bin++) {
        float4 w = __ldg(&W1v[bin * 128 + h4]);
#pragma unroll
        for (int k = 0; k < 16; k++) {
            float p = pooled[(rg * 16 + k) * BINS + bin];
            acc[k].x = fmaf(p, w.x, acc[k].x);
            acc[k].y = fmaf(p, w.y, acc[k].y);
            acc[k].z = fmaf(p, w.z, acc[k].z);
            acc[k].w = fmaf(p, w.w, acc[k].w);
        }
    }
    float4* U4 = (float4*)g_U;
#pragma unroll
    for (int k = 0; k < 16; k++)
        U4[(size_t)(br0 + rg * 16 + k) * 128 + h4] = acc[k];
}

// ---------------- kernel 5: V[i,:] = cond[i,:] @ W1[32:35,:] + b1 ----------------
__global__ __launch_bounds__(256) void v_kernel(const float* __restrict__ cond,
                                                const float* __restrict__ W1,
                                                const float* __restrict__ b1) {
    int idx = blockIdx.x * blockDim.x + threadIdx.x;   // over N * 128 float4
    int i = idx >> 7, h4 = idx & 127;
    float c0 = __ldg(&cond[i * 3 + 0]);
    float c1 = __ldg(&cond[i * 3 + 1]);
    float c2 = __ldg(&cond[i * 3 + 2]);
    const float4* W1r = (const float4*)(W1 + 32 * HH);
    float4 w0 = __ldg(&W1r[h4]), w1 = __ldg(&W1r[128 + h4]), w2 = __ldg(&W1r[256 + h4]);
    float4 bb = __ldg(&((const float4*)b1)[h4]);
    float4 v;
    v.x = fmaf(c0, w0.x, fmaf(c1, w1.x, fmaf(c2, w2.x, bb.x)));
    v.y = fmaf(c0, w0.y, fmaf(c1, w1.y, fmaf(c2, w2.y, bb.y)));
    v.z = fmaf(c0, w0.z, fmaf(c1, w1.z, fmaf(c2, w2.z, bb.z)));
    v.w = fmaf(c0, w0.w, fmaf(c1, w1.w, fmaf(c2, w2.w, bb.w)));
    ((float4*)g_V)[idx] = v;
}

// ---------------- kernel 6: main — warp per (b, r) pair, U in registers ----------------
// p = global warp id; r = p>>4 (16 consecutive warps share r -> V L1 reuse), b = p&15.
// start found by warp-uniform binary search on sorted seg.
__global__ __launch_bounds__(256) void main_kernel(const int* __restrict__ seg,
                                                   float* __restrict__ out) {
    int warp = threadIdx.x >> 5, lane = threadIdx.x & 31;
    int p = blockIdx.x * 8 + warp;
    int r = p >> 4, b = p & 15;

    int cnt = g_cnt[r];
    if (cnt == 0) return;

    // binary search: first index with seg[idx] >= r (uniform across warp)
    int lo = 0, hi = NN;
    while (lo < hi) {
        int mid = (lo + hi) >> 1;
        if (__ldg(&seg[mid]) < r) lo = mid + 1; else hi = mid;
    }
    int start = lo;

    // U row in registers: lane owns h = {q*128 + lane*4 .. +3} for q=0..3
    const float4* U4 = (const float4*)g_U + (size_t)(b * RR + r) * 128;
    const float4* W2p4 = (const float4*)g_W2p;
    float4 ur[4], p0[4], p1[4], p2[4];
#pragma unroll
    for (int q = 0; q < 4; q++) {
        int hq = q * 32 + lane;
        ur[q] = __ldg(&U4[hq]);
        p0[q] = __ldg(&W2p4[hq]);
        p1[q] = __ldg(&W2p4[128 + hq]);
        p2[q] = __ldg(&W2p4[256 + hq]);
    }
    float bp0 = g_b2p[0], bp1 = g_b2p[1], bp2 = g_b2p[2];

    const float4* V4 = (const float4*)g_V;
    for (int a = 0; a < cnt; a++) {
        int i = start + a;
        const float4* Vb = V4 + (size_t)i * 128;
        float a0 = 0.f, a1 = 0.f, a2 = 0.f;
#pragma unroll
        for (int q = 0; q < 4; q++) {
            float4 v = __ldg(&Vb[q * 32 + lane]);
            float z;
            z = fmaxf(ur[q].x + v.x, 0.f); a0 = fmaf(z, p0[q].x, a0); a1 = fmaf(z, p1[q].x, a1); a2 = fmaf(z, p2[q].x, a2);
            z = fmaxf(ur[q].y + v.y, 0.f); a0 = fmaf(z, p0[q].y, a0); a1 = fmaf(z, p1[q].y, a1); a2 = fmaf(z, p2[q].y, a2);
            z = fmaxf(ur[q].z + v.z, 0.f); a0 = fmaf(z, p0[q].z, a0); a1 = fmaf(z, p1[q].z, a1); a2 = fmaf(z, p2[q].z, a2);
            z = fmaxf(ur[q].w + v.w, 0.f); a0 = fmaf(z, p0[q].w, a0); a1 = fmaf(z, p1[q].w, a1); a2 = fmaf(z, p2[q].w, a2);
        }
#pragma unroll
        for (int off = 16; off; off >>= 1) {
            a0 += __shfl_xor_sync(0xffffffffu, a0, off);
            a1 += __shfl_xor_sync(0xffffffffu, a1, off);
            a2 += __shfl_xor_sync(0xffffffffu, a2, off);
        }
        // single predicated store: lanes 0..2 write the 3 outputs
        float val = (lane == 0) ? (a0 + bp0) : ((lane == 1) ? (a1 + bp1) : (a2 + bp2));
        if (lane < 3) out[((size_t)b * NN + i) * 3 + lane] = val;
    }
}

// ---------------- launch ----------------
extern "C" void kernel_launch(void* const* d_in, const int* in_sizes, int n_in,
                              void* d_out, int out_size) {
    const float* x       = (const float*)d_in[0];
    const float* cond    = (const float*)d_in[1];
    const int*   seg     = (const int*)  d_in[2];
    const float* W1      = (const float*)d_in[3];
    const float* b1      = (const float*)d_in[4];
    const float* gamma   = (const float*)d_in[5];
    const float* beta    = (const float*)d_in[6];
    const float* bn_mean = (const float*)d_in[7];
    const float* bn_var  = (const float*)d_in[8];
    const float* W2      = (const float*)d_in[9];
    const float* b2      = (const float*)d_in[10];
    float* out = (float*)d_out;

    zero_kernel<<<(BB * RR * BINS + 255) / 256, 256>>>();
    count_kernel<<<NN / 256, 256>>>(seg);
    binsum_kernel<<<(BB * NN) / 16, 256>>>(x, seg);
    w2p_kernel<<<1, HH>>>(gamma, beta, bn_mean, bn_var, W2, b2);
    u_kernel<<<(BB * RR) / 32, 256>>>(W1);
    v_kernel<<<(NN * (HH / 4)) / 256, 256>>>(cond, W1, b1);
    main_kernel<<<(BB * RR) / 8, 256>>>(seg, out);
}

// round 11
// speedup vs baseline: 2.5447x; 1.3272x over previous
#include <cuda_runtime.h>
#include <cuda_bf16.h>

#define BB   16
#define NN   16384
#define RR   1024
#define DD   320
#define BINS 32
#define HH   512
#define EPSV 1e-5f

// ---------------- scratch (device globals; no allocation allowed) ----------------
__device__ float g_S[BB * RR * BINS];   // segment bin sums (2 MB), [br][bin]
__device__ int   g_off[RR + 1];         // segment start offsets (from sorted seg)
__device__ float g_W2p[3 * HH];         // folded W2, SoA [c][h]
__device__ float g_b2p[3];

// ---------------- kernel 0: zero accumulators ----------------
__global__ void zero_kernel() {
    int idx = blockIdx.x * blockDim.x + threadIdx.x;
    if (idx < BB * RR * BINS) g_S[idx] = 0.0f;
    if (idx < 3) g_b2p[idx] = 0.0f;
}

// ---------------- kernel 1: segment offsets via binary search on sorted seg ----------------
__global__ void off_kernel(const int* __restrict__ seg) {
    int r = blockIdx.x * blockDim.x + threadIdx.x;
    if (r > RR) return;
    if (r == RR) { g_off[RR] = NN; return; }
    int lo = 0, hi = NN;                 // first idx with seg[idx] >= r
    while (lo < hi) {
        int mid = (lo + hi) >> 1;
        if (__ldg(&seg[mid]) < r) lo = mid + 1; else hi = mid;
    }
    g_off[r] = lo;
}

// ---------------- kernel 2: per-row 10-wide bin sums + segment atomics ----------------
__global__ __launch_bounds__(256) void binsum_kernel(const float* __restrict__ x,
                                                     const int* __restrict__ seg) {
    __shared__ float4 smf4[16 * 80];   // 16 rows x 320 floats = 20KB
    float* sm = (float*)smf4;
    int row0 = blockIdx.x * 16;
    const float4* x4 = (const float4*)x;
#pragma unroll
    for (int k = 0; k < 5; k++) {
        int e = k * 256 + threadIdx.x;          // 0..1279
        int rr = e / 80, c4 = e % 80;
        smf4[rr * 80 + c4] = x4[(size_t)(row0 + rr) * 80 + c4];
    }
    __syncthreads();
#pragma unroll
    for (int t = 0; t < 2; t++) {
        int task = t * 256 + threadIdx.x;       // 0..511 = 16 rows x 32 bins
        int rr = task >> 5, bin = task & 31;
        int row = row0 + rr;
        int b = row >> 14;                      // row / NN
        int i = row & (NN - 1);
        float s = 0.0f;
#pragma unroll
        for (int j = 0; j < 10; j++) s += sm[rr * 320 + bin * 10 + j];
        atomicAdd(&g_S[((b << 10) + seg[i]) * BINS + bin], s);
    }
}

// ---------------- kernel 3: fold batchnorm into W2 (fast: shfl + atomics) ----------------
__global__ __launch_bounds__(HH) void w2p_kernel(const float* __restrict__ gamma,
                                                 const float* __restrict__ beta,
                                                 const float* __restrict__ bn_mean,
                                                 const float* __restrict__ bn_var,
                                                 const float* __restrict__ W2,
                                                 const float* __restrict__ b2) {
    int h = threadIdx.x;
    int lane = h & 31;
    float s = rsqrtf(bn_var[h] + EPSV) * gamma[h];
    float t = beta[h] - bn_mean[h] * s;
    float part[3];
#pragma unroll
    for (int c = 0; c < 3; c++) {
        float w = W2[h * 3 + c];
        g_W2p[c * HH + h] = w * s;
        part[c] = t * w;
#pragma unroll
        for (int off = 16; off; off >>= 1)
            part[c] += __shfl_xor_sync(0xffffffffu, part[c], off);
        if (lane == 0) atomicAdd(&g_b2p[c], part[c]);
    }
    if (h < 3) atomicAdd(&g_b2p[h], b2[h]);
}

// ---------------- kernel 4: mega — block per segment r ----------------
// Phase U: Us[16][512] (smem) = pooled[16][32] @ W1[0:32,:]
// Phase B: warp per atom; lane owns 16 h; W2p in regs; V computed inline;
//          per (b,atom): 4 LDS.128 of U + 80 FMA + 15 shfl + predicated store.
#define MEGA2_SMEM (16 * 129 * 16 + 16 * BINS * 4)

__global__ __launch_bounds__(256) void mega2_kernel(const float* __restrict__ cond,
                                                    const float* __restrict__ W1,
                                                    const float* __restrict__ b1,
                                                    float* __restrict__ out) {
    extern __shared__ float4 dyn[];
    float4* Us4   = dyn;                        // [16][129]
    float*  pooled = (float*)(Us4 + 16 * 129);  // [16][32]

    int r = blockIdx.x;
    int start = __ldg(&g_off[r]);
    int cnt   = __ldg(&g_off[r + 1]) - start;
    if (cnt == 0) return;
    int tid = threadIdx.x;

    // pooled (scaled) into smem — coalesced on bin
    float inv = 1.0f / (10.0f * (float)cnt);
    for (int e = tid; e < BB * BINS; e += 256) {
        int b = e >> 5, bin = e & 31;
        pooled[e] = g_S[(size_t)((b << 10) + r) * BINS + bin] * inv;
    }
    __syncthreads();

    // ---- phase U ----
    {
        int hq = tid & 127, bh = tid >> 7;      // bh in {0,1}
        const float4* W1v = (const float4*)W1;
        float4 acc[8];
#pragma unroll
        for (int k = 0; k < 8; k++) acc[k] = make_float4(0.f, 0.f, 0.f, 0.f);
#pragma unroll 4
        for (int bin = 0; bin < BINS; bin++) {
            float4 w = __ldg(&W1v[bin * 128 + hq]);
#pragma unroll
            for (int k = 0; k < 8; k++) {
                float p = pooled[(bh * 8 + k) * BINS + bin];
                acc[k].x = fmaf(p, w.x, acc[k].x);
                acc[k].y = fmaf(p, w.y, acc[k].y);
                acc[k].z = fmaf(p, w.z, acc[k].z);
                acc[k].w = fmaf(p, w.w, acc[k].w);
            }
        }
#pragma unroll
        for (int k = 0; k < 8; k++) Us4[(bh * 8 + k) * 129 + hq] = acc[k];
    }
    __syncthreads();

    // ---- phase B ----
    int warp = tid >> 5, lane = tid & 31;
    const float4* W2p4 = (const float4*)g_W2p;
    const float4* W1c  = (const float4*)(W1 + BINS * HH);
    const float4* b14  = (const float4*)b1;
    float4 p0[4], p1[4], p2[4];
#pragma unroll
    for (int q = 0; q < 4; q++) {
        int hq = q * 32 + lane;
        p0[q] = __ldg(&W2p4[hq]);
        p1[q] = __ldg(&W2p4[128 + hq]);
        p2[q] = __ldg(&W2p4[256 + hq]);
    }
    float bp0 = g_b2p[0], bp1 = g_b2p[1], bp2 = g_b2p[2];

    for (int a = warp; a < cnt; a += 8) {
        int i = start + a;
        float c0 = __ldg(&cond[i * 3 + 0]);
        float c1 = __ldg(&cond[i * 3 + 1]);
        float c2 = __ldg(&cond[i * 3 + 2]);
        float4 vr[4];
#pragma unroll
        for (int q = 0; q < 4; q++) {
            int hq = q * 32 + lane;
            float4 w0 = __ldg(&W1c[hq]);
            float4 w1 = __ldg(&W1c[128 + hq]);
            float4 w2 = __ldg(&W1c[256 + hq]);
            float4 bv = __ldg(&b14[hq]);
            vr[q].x = fmaf(c0, w0.x, fmaf(c1, w1.x, fmaf(c2, w2.x, bv.x)));
            vr[q].y = fmaf(c0, w0.y, fmaf(c1, w1.y, fmaf(c2, w2.y, bv.y)));
            vr[q].z = fmaf(c0, w0.z, fmaf(c1, w1.z, fmaf(c2, w2.z, bv.z)));
            vr[q].w = fmaf(c0, w0.w, fmaf(c1, w1.w, fmaf(c2, w2.w, bv.w)));
        }
#pragma unroll 1
        for (int b = 0; b < BB; b++) {
            const float4* Ub = Us4 + b * 129;
            float a0 = 0.f, a1 = 0.f, a2 = 0.f;
#pragma unroll
            for (int q = 0; q < 4; q++) {
                float4 u = Ub[q * 32 + lane];     // conflict-free LDS.128
                float z;
                z = fmaxf(u.x + vr[q].x, 0.f); a0 = fmaf(z, p0[q].x, a0); a1 = fmaf(z, p1[q].x, a1); a2 = fmaf(z, p2[q].x, a2);
                z = fmaxf(u.y + vr[q].y, 0.f); a0 = fmaf(z, p0[q].y, a0); a1 = fmaf(z, p1[q].y, a1); a2 = fmaf(z, p2[q].y, a2);
                z = fmaxf(u.z + vr[q].z, 0.f); a0 = fmaf(z, p0[q].z, a0); a1 = fmaf(z, p1[q].z, a1); a2 = fmaf(z, p2[q].z, a2);
                z = fmaxf(u.w + vr[q].w, 0.f); a0 = fmaf(z, p0[q].w, a0); a1 = fmaf(z, p1[q].w, a1); a2 = fmaf(z, p2[q].w, a2);
            }
#pragma unroll
            for (int off = 16; off; off >>= 1) {
                a0 += __shfl_xor_sync(0xffffffffu, a0, off);
                a1 += __shfl_xor_sync(0xffffffffu, a1, off);
                a2 += __shfl_xor_sync(0xffffffffu, a2, off);
            }
            float val = (lane == 0) ? (a0 + bp0) : ((lane == 1) ? (a1 + bp1) : (a2 + bp2));
            if (lane < 3) out[((size_t)b * NN + i) * 3 + lane] = val;
        }
    }
}

// ---------------- launch ----------------
extern "C" void kernel_launch(void* const* d_in, const int* in_sizes, int n_in,
                              void* d_out, int out_size) {
    const float* x       = (const float*)d_in[0];
    const float* cond    = (const float*)d_in[1];
    const int*   seg     = (const int*)  d_in[2];
    const float* W1      = (const float*)d_in[3];
    const float* b1      = (const float*)d_in[4];
    const float* gamma   = (const float*)d_in[5];
    const float* beta    = (const float*)d_in[6];
    const float* bn_mean = (const float*)d_in[7];
    const float* bn_var  = (const float*)d_in[8];
    const float* W2      = (const float*)d_in[9];
    const float* b2      = (const float*)d_in[10];
    float* out = (float*)d_out;

    cudaFuncSetAttribute(mega2_kernel, cudaFuncAttributeMaxDynamicSharedMemorySize, MEGA2_SMEM);

    zero_kernel<<<(BB * RR * BINS + 255) / 256, 256>>>();
    off_kernel<<<(RR + 1 + 255) / 256, 256>>>(seg);
    binsum_kernel<<<(BB * NN) / 16, 256>>>(x, seg);
    w2p_kernel<<<1, HH>>>(gamma, beta, bn_mean, bn_var, W2, b2);
    mega2_kernel<<<RR, 256, MEGA2_SMEM>>>(cond, W1, b1, out);
}